// round 11
// baseline (speedup 1.0000x reference)
#include <cuda_runtime.h>
#include <cuda_fp16.h>

#define NN 100000
#define EE 3200000
#define D 16
#define RS 32                 // accumulator row stride (floats) = 128B = one line
#define ATTN_SLOPE 0.2f
#define ACT_SLOPE 0.01f

// ---- scratch (device globals; no allocation allowed) ----
__device__ float  g_fs[NN * D];       // feat_src rows (fp32: feeds numer directly)
__device__ __half g_fdh[NN * D];      // feat_dst rows (fp16: only feeds the score)
__device__ float  g_acc[NN * RS];     // [numer[16], denom, pad...] one 128B line per node

static __device__ __forceinline__ float lrelu(float x, float s) {
    return x >= 0.0f ? x : s * x;
}

static __device__ __forceinline__ uint2 pack_half4(float4 v) {
    __half2 h01 = __floats2half2_rn(v.x, v.y);
    __half2 h23 = __floats2half2_rn(v.z, v.w);
    uint2 u;
    u.x = *reinterpret_cast<unsigned int*>(&h01);
    u.y = *reinterpret_cast<unsigned int*>(&h23);
    return u;
}
static __device__ __forceinline__ float4 unpack_half4(uint2 u) {
    float2 a = __half22float2(*reinterpret_cast<__half2*>(&u.x));
    float2 b = __half22float2(*reinterpret_cast<__half2*>(&u.y));
    return make_float4(a.x, a.y, b.x, b.y);
}

// ============================================================
// node kernels: 4 threads per node, each owns one float4 quarter
// ============================================================

// ---- layer 1 prologue: feats + accumulator init ----
__global__ void k_feat1(const float* __restrict__ h,
                        const float* __restrict__ Wsrc, const float* __restrict__ bsrc,
                        const float* __restrict__ Wdst, const float* __restrict__ bdst,
                        int n)
{
    __shared__ float4 sWs[D * 4], sWd[D * 4];   // [k][q]
    __shared__ float4 sbs[4], sbd[4];
    if (threadIdx.x < D * 4) {
        sWs[threadIdx.x] = reinterpret_cast<const float4*>(Wsrc)[threadIdx.x];
        sWd[threadIdx.x] = reinterpret_cast<const float4*>(Wdst)[threadIdx.x];
    }
    if (threadIdx.x < 4) {
        sbs[threadIdx.x] = reinterpret_cast<const float4*>(bsrc)[threadIdx.x];
        sbd[threadIdx.x] = reinterpret_cast<const float4*>(bdst)[threadIdx.x];
    }
    __syncthreads();
    int t  = blockIdx.x * blockDim.x + threadIdx.x;
    int nd = t >> 2;
    int q  = t & 3;
    if (nd >= n) return;

    const float4* hr = reinterpret_cast<const float4*>(h + (size_t)nd * D);
    float hv[D];
#pragma unroll
    for (int i = 0; i < 4; i++) {
        float4 v = hr[i];
        hv[4*i+0] = v.x; hv[4*i+1] = v.y; hv[4*i+2] = v.z; hv[4*i+3] = v.w;
    }
    float4 fs = sbs[q], fd = sbd[q];
#pragma unroll
    for (int k = 0; k < D; k++) {
        float hk = hv[k];
        float4 ws = sWs[k*4 + q];
        float4 wd = sWd[k*4 + q];
        fs.x = fmaf(hk, ws.x, fs.x); fs.y = fmaf(hk, ws.y, fs.y);
        fs.z = fmaf(hk, ws.z, fs.z); fs.w = fmaf(hk, ws.w, fs.w);
        fd.x = fmaf(hk, wd.x, fd.x); fd.y = fmaf(hk, wd.y, fd.y);
        fd.z = fmaf(hk, wd.z, fd.z); fd.w = fmaf(hk, wd.w, fd.w);
    }
    reinterpret_cast<float4*>(g_fs + (size_t)nd * D)[q] = fs;
    reinterpret_cast<uint2*>(g_fdh + (size_t)nd * D)[q] = pack_half4(fd);
    float4 z = make_float4(0.f, 0.f, 0.f, 0.f);
    float4* pa = reinterpret_cast<float4*>(g_acc + (size_t)nd * RS);
    pa[q] = z; pa[q + 4] = z;
}

// ---- layer-1 epilogue fused with layer-2 feats ----
__global__ void k_mid(const float* __restrict__ Wsrc, const float* __restrict__ bsrc,
                      const float* __restrict__ Wdst, const float* __restrict__ bdst,
                      int n)
{
    __shared__ float4 sWs[D * 4], sWd[D * 4];
    __shared__ float4 sbs[4], sbd[4];
    if (threadIdx.x < D * 4) {
        sWs[threadIdx.x] = reinterpret_cast<const float4*>(Wsrc)[threadIdx.x];
        sWd[threadIdx.x] = reinterpret_cast<const float4*>(Wdst)[threadIdx.x];
    }
    if (threadIdx.x < 4) {
        sbs[threadIdx.x] = reinterpret_cast<const float4*>(bsrc)[threadIdx.x];
        sbd[threadIdx.x] = reinterpret_cast<const float4*>(bdst)[threadIdx.x];
    }
    __syncthreads();
    int t  = blockIdx.x * blockDim.x + threadIdx.x;
    int nd = t >> 2;
    int q  = t & 3;
    if (nd >= n) return;

    const float* row = g_acc + (size_t)nd * RS;
    float dn  = row[16];
    float inv = dn > 0.0f ? 1.0f / dn : 0.0f;
    const float4* np = reinterpret_cast<const float4*>(row);
    float hv[D];
#pragma unroll
    for (int i = 0; i < 4; i++) {
        float4 v = np[i];
        hv[4*i+0] = lrelu(v.x * inv, ACT_SLOPE);
        hv[4*i+1] = lrelu(v.y * inv, ACT_SLOPE);
        hv[4*i+2] = lrelu(v.z * inv, ACT_SLOPE);
        hv[4*i+3] = lrelu(v.w * inv, ACT_SLOPE);
    }
    float4 fs = sbs[q], fd = sbd[q];
#pragma unroll
    for (int k = 0; k < D; k++) {
        float hk = hv[k];
        float4 ws = sWs[k*4 + q];
        float4 wd = sWd[k*4 + q];
        fs.x = fmaf(hk, ws.x, fs.x); fs.y = fmaf(hk, ws.y, fs.y);
        fs.z = fmaf(hk, ws.z, fs.z); fs.w = fmaf(hk, ws.w, fs.w);
        fd.x = fmaf(hk, wd.x, fd.x); fd.y = fmaf(hk, wd.y, fd.y);
        fd.z = fmaf(hk, wd.z, fd.z); fd.w = fmaf(hk, wd.w, fd.w);
    }
    reinterpret_cast<float4*>(g_fs + (size_t)nd * D)[q] = fs;
    reinterpret_cast<uint2*>(g_fdh + (size_t)nd * D)[q] = pack_half4(fd);
    float4 z = make_float4(0.f, 0.f, 0.f, 0.f);
    float4* pa = reinterpret_cast<float4*>(g_acc + (size_t)nd * RS);
    pa[q] = z; pa[q + 4] = z;
}

// ============================================================
// fused edge pass: 8 lanes per octet, 2 edges per octet (sequential).
// Lanes 0-3 gather + score; lane 4 rides the SAME red.v4 instruction
// carrying the denom contribution into the same 128B accumulator line.
// Softmax without max-shift (shift cancels exactly in numer/denom).
// ============================================================
__global__ void k_edge(const int* __restrict__ src, const int* __restrict__ dst,
                       const float* __restrict__ attn, int e)
{
    int t     = blockIdx.x * blockDim.x + threadIdx.x;
    int octet = t >> 3;
    int ol    = t & 7;
    int q     = ol & 3;
    int e0    = octet * 2;
    if (e0 >= e) return;
    bool two  = (e0 + 1) < e;
    bool ld   = ol < 4;

    float4 a = __ldg(reinterpret_cast<const float4*>(attn) + q);

    int2 sv, dv;
    if (two) {
        sv = __ldg(reinterpret_cast<const int2*>(src + e0));
        dv = __ldg(reinterpret_cast<const int2*>(dst + e0));
    } else {
        sv.x = __ldg(src + e0); sv.y = sv.x;
        dv.x = __ldg(dst + e0); dv.y = dv.x;
    }

    // gathers only on lanes 0-3 (predicated lanes emit no requests)
    float4 el0 = make_float4(0.f, 0.f, 0.f, 0.f), el1 = el0, ed0 = el0, ed1 = el0;
    if (ld) {
        el0 = *(reinterpret_cast<const float4*>(g_fs + (size_t)sv.x * D) + q);
        uint2 eu0 = *(reinterpret_cast<const uint2*>(g_fdh + (size_t)dv.x * D) + q);
        el1 = *(reinterpret_cast<const float4*>(g_fs + (size_t)sv.y * D) + q);
        uint2 eu1 = *(reinterpret_cast<const uint2*>(g_fdh + (size_t)dv.y * D) + q);
        ed0 = unpack_half4(eu0);
        ed1 = unpack_half4(eu1);
    }

    float p0 = lrelu(el0.x + ed0.x, ATTN_SLOPE) * a.x
             + lrelu(el0.y + ed0.y, ATTN_SLOPE) * a.y
             + lrelu(el0.z + ed0.z, ATTN_SLOPE) * a.z
             + lrelu(el0.w + ed0.w, ATTN_SLOPE) * a.w;
    float p1 = lrelu(el1.x + ed1.x, ATTN_SLOPE) * a.x
             + lrelu(el1.y + ed1.y, ATTN_SLOPE) * a.y
             + lrelu(el1.z + ed1.z, ATTN_SLOPE) * a.z
             + lrelu(el1.w + ed1.w, ATTN_SLOPE) * a.w;

    // reduce within each quartet (lanes 0-3 of the octet end up with full score)
    p0 += __shfl_xor_sync(0xFFFFFFFFu, p0, 1);
    p0 += __shfl_xor_sync(0xFFFFFFFFu, p0, 2);
    p1 += __shfl_xor_sync(0xFFFFFFFFu, p1, 1);
    p1 += __shfl_xor_sync(0xFFFFFFFFu, p1, 2);

    float ex0 = __expf(p0);
    float ex1 = __expf(p1);

    // broadcast the valid score-exp from the octet's lane 0 to lane 4
    int wl   = threadIdx.x & 31;
    int srcl = wl & ~7;
    float bx0 = __shfl_sync(0xFFFFFFFFu, ex0, srcl);
    float bx1 = __shfl_sync(0xFFFFFFFFu, ex1, srcl);
    if (ol == 4) { ex0 = bx0; ex1 = bx1; }

    if (ol <= 4) {
        // lane q<4: numer quarter; lane 4: denom at row+16 — same 128B line,
        // same red.v4 instruction => no extra wavefront for denom.
        float4 v0 = (ol == 4) ? make_float4(ex0, 0.f, 0.f, 0.f)
                              : make_float4(ex0 * el0.x, ex0 * el0.y,
                                            ex0 * el0.z, ex0 * el0.w);
        float* pn0 = g_acc + (size_t)dv.x * RS + ol * 4;
        asm volatile("red.global.add.v4.f32 [%0], {%1, %2, %3, %4};"
                     :: "l"(pn0), "f"(v0.x), "f"(v0.y), "f"(v0.z), "f"(v0.w)
                     : "memory");
        if (two) {
            float4 v1 = (ol == 4) ? make_float4(ex1, 0.f, 0.f, 0.f)
                                  : make_float4(ex1 * el1.x, ex1 * el1.y,
                                                ex1 * el1.z, ex1 * el1.w);
            float* pn1 = g_acc + (size_t)dv.y * RS + ol * 4;
            asm volatile("red.global.add.v4.f32 [%0], {%1, %2, %3, %4};"
                         :: "l"(pn1), "f"(v1.x), "f"(v1.y), "f"(v1.z), "f"(v1.w)
                         : "memory");
        }
    }
}

// ---- layer-2 epilogue -> output ----
__global__ void k_fin(float* __restrict__ out, int n)
{
    int t  = blockIdx.x * blockDim.x + threadIdx.x;
    int nd = t >> 2;
    int q  = t & 3;
    if (nd >= n) return;
    const float* row = g_acc + (size_t)nd * RS;
    float dn  = row[16];
    float inv = dn > 0.0f ? 1.0f / dn : 0.0f;
    float4 v = reinterpret_cast<const float4*>(row)[q];
    reinterpret_cast<float4*>(out + (size_t)nd * D)[q] =
        make_float4(lrelu(v.x * inv, ACT_SLOPE),
                    lrelu(v.y * inv, ACT_SLOPE),
                    lrelu(v.z * inv, ACT_SLOPE),
                    lrelu(v.w * inv, ACT_SLOPE));
}

extern "C" void kernel_launch(void* const* d_in, const int* in_sizes, int n_in,
                              void* d_out, int out_size)
{
    const float* emb = (const float*)d_in[0];
    const int*   src1 = (const int*)d_in[1];
    const int*   dst1 = (const int*)d_in[2];
    const int*   src2 = (const int*)d_in[3];
    const int*   dst2 = (const int*)d_in[4];
    const float* Ws1 = (const float*)d_in[5];
    const float* bs1 = (const float*)d_in[6];
    const float* Wd1 = (const float*)d_in[7];
    const float* bd1 = (const float*)d_in[8];
    const float* at1 = (const float*)d_in[9];
    const float* Ws2 = (const float*)d_in[10];
    const float* bs2 = (const float*)d_in[11];
    const float* Wd2 = (const float*)d_in[12];
    const float* bd2 = (const float*)d_in[13];
    const float* at2 = (const float*)d_in[14];
    float* out = (float*)d_out;

    int n  = in_sizes[0] / D;
    int e1 = in_sizes[1];
    int e2 = in_sizes[3];

    dim3 tb(256);
    dim3 nb((unsigned)(((size_t)n * 4 + 255) / 256));
    // 8 lanes per octet, 2 edges per octet
    long long g1 = ((long long)(e1 + 1) / 2) * 8;
    long long g2 = ((long long)(e2 + 1) / 2) * 8;
    dim3 eb1((unsigned)((g1 + 255) / 256));
    dim3 eb2((unsigned)((g2 + 255) / 256));

    // layer 1
    k_feat1<<<nb, tb>>>(emb, Ws1, bs1, Wd1, bd1, n);
    k_edge <<<eb1, tb>>>(src1, dst1, at1, e1);
    // layer-1 epilogue + layer-2 feats
    k_mid  <<<nb, tb>>>(Ws2, bs2, Wd2, bd2, n);
    // layer 2
    k_edge <<<eb2, tb>>>(src2, dst2, at2, e2);
    k_fin  <<<nb, tb>>>(out, n);
}

// round 12
// speedup vs baseline: 1.0015x; 1.0015x over previous
#include <cuda_runtime.h>
#include <cuda_fp16.h>

#define NN 100000
#define EE 3200000
#define D 16
#define RS 32                 // accumulator row stride (floats) = 128B = one line
#define ATTN_SLOPE 0.2f
#define ACT_SLOPE 0.01f

// ---- scratch (device globals; no allocation allowed) ----
__device__ float  g_fs[NN * D];       // feat_src rows (fp32: feeds numer directly)
__device__ __half g_fdh[NN * D];      // feat_dst rows (fp16: only feeds the score)
__device__ float  g_acc[NN * RS];     // [numer[16], denom, pad...] one 128B line per node

static __device__ __forceinline__ float lrelu(float x, float s) {
    return x >= 0.0f ? x : s * x;
}

static __device__ __forceinline__ uint2 pack_half4(float4 v) {
    __half2 h01 = __floats2half2_rn(v.x, v.y);
    __half2 h23 = __floats2half2_rn(v.z, v.w);
    uint2 u;
    u.x = *reinterpret_cast<unsigned int*>(&h01);
    u.y = *reinterpret_cast<unsigned int*>(&h23);
    return u;
}
static __device__ __forceinline__ float4 unpack_half4(uint2 u) {
    float2 a = __half22float2(*reinterpret_cast<__half2*>(&u.x));
    float2 b = __half22float2(*reinterpret_cast<__half2*>(&u.y));
    return make_float4(a.x, a.y, b.x, b.y);
}

// ============================================================
// node kernels: 4 threads per node, each owns one float4 quarter
// ============================================================

__global__ void k_feat1(const float* __restrict__ h,
                        const float* __restrict__ Wsrc, const float* __restrict__ bsrc,
                        const float* __restrict__ Wdst, const float* __restrict__ bdst,
                        int n)
{
    __shared__ float4 sWs[D * 4], sWd[D * 4];   // [k][q]
    __shared__ float4 sbs[4], sbd[4];
    if (threadIdx.x < D * 4) {
        sWs[threadIdx.x] = reinterpret_cast<const float4*>(Wsrc)[threadIdx.x];
        sWd[threadIdx.x] = reinterpret_cast<const float4*>(Wdst)[threadIdx.x];
    }
    if (threadIdx.x < 4) {
        sbs[threadIdx.x] = reinterpret_cast<const float4*>(bsrc)[threadIdx.x];
        sbd[threadIdx.x] = reinterpret_cast<const float4*>(bdst)[threadIdx.x];
    }
    __syncthreads();
    int t  = blockIdx.x * blockDim.x + threadIdx.x;
    int nd = t >> 2;
    int q  = t & 3;
    if (nd >= n) return;

    const float4* hr = reinterpret_cast<const float4*>(h + (size_t)nd * D);
    float hv[D];
#pragma unroll
    for (int i = 0; i < 4; i++) {
        float4 v = hr[i];
        hv[4*i+0] = v.x; hv[4*i+1] = v.y; hv[4*i+2] = v.z; hv[4*i+3] = v.w;
    }
    float4 fs = sbs[q], fd = sbd[q];
#pragma unroll
    for (int k = 0; k < D; k++) {
        float hk = hv[k];
        float4 ws = sWs[k*4 + q];
        float4 wd = sWd[k*4 + q];
        fs.x = fmaf(hk, ws.x, fs.x); fs.y = fmaf(hk, ws.y, fs.y);
        fs.z = fmaf(hk, ws.z, fs.z); fs.w = fmaf(hk, ws.w, fs.w);
        fd.x = fmaf(hk, wd.x, fd.x); fd.y = fmaf(hk, wd.y, fd.y);
        fd.z = fmaf(hk, wd.z, fd.z); fd.w = fmaf(hk, wd.w, fd.w);
    }
    reinterpret_cast<float4*>(g_fs + (size_t)nd * D)[q] = fs;
    reinterpret_cast<uint2*>(g_fdh + (size_t)nd * D)[q] = pack_half4(fd);
    float4 z = make_float4(0.f, 0.f, 0.f, 0.f);
    float4* pa = reinterpret_cast<float4*>(g_acc + (size_t)nd * RS);
    pa[q] = z; pa[q + 4] = z;
}

__global__ void k_mid(const float* __restrict__ Wsrc, const float* __restrict__ bsrc,
                      const float* __restrict__ Wdst, const float* __restrict__ bdst,
                      int n)
{
    __shared__ float4 sWs[D * 4], sWd[D * 4];
    __shared__ float4 sbs[4], sbd[4];
    if (threadIdx.x < D * 4) {
        sWs[threadIdx.x] = reinterpret_cast<const float4*>(Wsrc)[threadIdx.x];
        sWd[threadIdx.x] = reinterpret_cast<const float4*>(Wdst)[threadIdx.x];
    }
    if (threadIdx.x < 4) {
        sbs[threadIdx.x] = reinterpret_cast<const float4*>(bsrc)[threadIdx.x];
        sbd[threadIdx.x] = reinterpret_cast<const float4*>(bdst)[threadIdx.x];
    }
    __syncthreads();
    int t  = blockIdx.x * blockDim.x + threadIdx.x;
    int nd = t >> 2;
    int q  = t & 3;
    if (nd >= n) return;

    const float* row = g_acc + (size_t)nd * RS;
    float dn  = row[16];
    float inv = dn > 0.0f ? 1.0f / dn : 0.0f;
    const float4* np = reinterpret_cast<const float4*>(row);
    float hv[D];
#pragma unroll
    for (int i = 0; i < 4; i++) {
        float4 v = np[i];
        hv[4*i+0] = lrelu(v.x * inv, ACT_SLOPE);
        hv[4*i+1] = lrelu(v.y * inv, ACT_SLOPE);
        hv[4*i+2] = lrelu(v.z * inv, ACT_SLOPE);
        hv[4*i+3] = lrelu(v.w * inv, ACT_SLOPE);
    }
    float4 fs = sbs[q], fd = sbd[q];
#pragma unroll
    for (int k = 0; k < D; k++) {
        float hk = hv[k];
        float4 ws = sWs[k*4 + q];
        float4 wd = sWd[k*4 + q];
        fs.x = fmaf(hk, ws.x, fs.x); fs.y = fmaf(hk, ws.y, fs.y);
        fs.z = fmaf(hk, ws.z, fs.z); fs.w = fmaf(hk, ws.w, fs.w);
        fd.x = fmaf(hk, wd.x, fd.x); fd.y = fmaf(hk, wd.y, fd.y);
        fd.z = fmaf(hk, wd.z, fd.z); fd.w = fmaf(hk, wd.w, fd.w);
    }
    reinterpret_cast<float4*>(g_fs + (size_t)nd * D)[q] = fs;
    reinterpret_cast<uint2*>(g_fdh + (size_t)nd * D)[q] = pack_half4(fd);
    float4 z = make_float4(0.f, 0.f, 0.f, 0.f);
    float4* pa = reinterpret_cast<float4*>(g_acc + (size_t)nd * RS);
    pa[q] = z; pa[q + 4] = z;
}

// ============================================================
// fused edge pass, R8 structure (4 lanes/edge, 2 rounds of 8
// edges per warp) + chunk-remapped reductions: the 40 red-chunks
// of a round (4 numer quarters + 1 denom per edge; denom lives in
// the same 128B acc line at float offset 16) are issued as one
// 32-lane red.v4 (7 lines) + one 8-lane red.v4 (2 lines) instead
// of numer-red (8 lines) + denom-red (8 lines): 9 wf vs 16 wf,
// same lane count, same arithmetic.
// Softmax without max-shift (shift cancels exactly in numer/denom).
// ============================================================

// issue the two chunk-remapped red.v4 instructions for one round.
// w = ex*el quarter (this lane), ex = edge weight, d = dst node.
static __device__ __forceinline__ void red_remap(float4 w, float ex, int d)
{
    const unsigned m = 0xFFFFFFFFu;
    int wl = threadIdx.x & 31;

    // ---- instruction 1: chunks c = wl (0..31) -> edge c/5, slot c%5 ----
    {
        int c  = wl;
        int eC = c / 5;           // 0..6
        int sC = c - eC * 5;      // 0..4
        int sl = eC * 4 + (sC < 4 ? sC : 0);
        float wx = __shfl_sync(m, w.x, sl);
        float wy = __shfl_sync(m, w.y, sl);
        float wz = __shfl_sync(m, w.z, sl);
        float ww = __shfl_sync(m, w.w, sl);
        float xs = __shfl_sync(m, ex,  sl);
        int   dd = __shfl_sync(m, d,   eC * 4);
        float4 v = (sC < 4) ? make_float4(wx, wy, wz, ww)
                            : make_float4(xs, 0.f, 0.f, 0.f);
        float* p = g_acc + (size_t)dd * RS + sC * 4;
        asm volatile("red.global.add.v4.f32 [%0], {%1, %2, %3, %4};"
                     :: "l"(p), "f"(v.x), "f"(v.y), "f"(v.z), "f"(v.w)
                     : "memory");
    }
    // ---- instruction 2: chunks c = 32+wl for wl<8 -> edges 6,7 ----
    {
        int c  = 32 + wl;
        int eC = c / 5;           // 6..12 (only wl<8 meaningful)
        int sC = c - eC * 5;
        int eCc = eC > 7 ? 7 : eC;
        int sl  = eCc * 4 + (sC < 4 ? sC : 0);
        float wx = __shfl_sync(m, w.x, sl);
        float wy = __shfl_sync(m, w.y, sl);
        float wz = __shfl_sync(m, w.z, sl);
        float ww = __shfl_sync(m, w.w, sl);
        float xs = __shfl_sync(m, ex,  sl);
        int   dd = __shfl_sync(m, d,   eCc * 4);
        if (wl < 8) {
            float4 v = (sC < 4) ? make_float4(wx, wy, wz, ww)
                                : make_float4(xs, 0.f, 0.f, 0.f);
            float* p = g_acc + (size_t)dd * RS + sC * 4;
            asm volatile("red.global.add.v4.f32 [%0], {%1, %2, %3, %4};"
                         :: "l"(p), "f"(v.x), "f"(v.y), "f"(v.z), "f"(v.w)
                         : "memory");
        }
    }
}

__global__ void k_edge(const int* __restrict__ src, const int* __restrict__ dst,
                       const float* __restrict__ attn, int e)
{
    int t      = blockIdx.x * blockDim.x + threadIdx.x;
    int warpId = t >> 5;
    int wl     = t & 31;
    int elane  = wl >> 2;     // edge slot 0..7 within round
    int q      = wl & 3;

    long long base = (long long)warpId * 16;
    if (base >= e) return;    // uniform across warp

    float4 a = __ldg(reinterpret_cast<const float4*>(attn) + q);

    long long i0 = base + elane;
    long long i1 = base + 8 + elane;
    bool v0 = i0 < e;
    bool v1 = i1 < e;
    int eid0 = (int)(v0 ? i0 : (e - 1));
    int eid1 = (int)(v1 ? i1 : (e - 1));

    int s0 = __ldg(src + eid0), d0 = __ldg(dst + eid0);
    int s1 = __ldg(src + eid1), d1 = __ldg(dst + eid1);

    // all 4 gathers in flight
    float4 el0 = *(reinterpret_cast<const float4*>(g_fs + (size_t)s0 * D) + q);
    uint2  eu0 = *(reinterpret_cast<const uint2*>(g_fdh + (size_t)d0 * D) + q);
    float4 el1 = *(reinterpret_cast<const float4*>(g_fs + (size_t)s1 * D) + q);
    uint2  eu1 = *(reinterpret_cast<const uint2*>(g_fdh + (size_t)d1 * D) + q);
    float4 ed0 = unpack_half4(eu0);
    float4 ed1 = unpack_half4(eu1);

    float p0 = lrelu(el0.x + ed0.x, ATTN_SLOPE) * a.x
             + lrelu(el0.y + ed0.y, ATTN_SLOPE) * a.y
             + lrelu(el0.z + ed0.z, ATTN_SLOPE) * a.z
             + lrelu(el0.w + ed0.w, ATTN_SLOPE) * a.w;
    float p1 = lrelu(el1.x + ed1.x, ATTN_SLOPE) * a.x
             + lrelu(el1.y + ed1.y, ATTN_SLOPE) * a.y
             + lrelu(el1.z + ed1.z, ATTN_SLOPE) * a.z
             + lrelu(el1.w + ed1.w, ATTN_SLOPE) * a.w;

    p0 += __shfl_xor_sync(0xFFFFFFFFu, p0, 1);
    p0 += __shfl_xor_sync(0xFFFFFFFFu, p0, 2);
    p1 += __shfl_xor_sync(0xFFFFFFFFu, p1, 1);
    p1 += __shfl_xor_sync(0xFFFFFFFFu, p1, 2);

    float ex0 = v0 ? __expf(p0) : 0.0f;   // invalid edges contribute 0
    float ex1 = v1 ? __expf(p1) : 0.0f;

    float4 w0 = make_float4(ex0 * el0.x, ex0 * el0.y, ex0 * el0.z, ex0 * el0.w);
    float4 w1 = make_float4(ex1 * el1.x, ex1 * el1.y, ex1 * el1.z, ex1 * el1.w);

    red_remap(w0, ex0, d0);
    red_remap(w1, ex1, d1);
}

// ---- layer-2 epilogue -> output ----
__global__ void k_fin(float* __restrict__ out, int n)
{
    int t  = blockIdx.x * blockDim.x + threadIdx.x;
    int nd = t >> 2;
    int q  = t & 3;
    if (nd >= n) return;
    const float* row = g_acc + (size_t)nd * RS;
    float dn  = row[16];
    float inv = dn > 0.0f ? 1.0f / dn : 0.0f;
    float4 v = reinterpret_cast<const float4*>(row)[q];
    reinterpret_cast<float4*>(out + (size_t)nd * D)[q] =
        make_float4(lrelu(v.x * inv, ACT_SLOPE),
                    lrelu(v.y * inv, ACT_SLOPE),
                    lrelu(v.z * inv, ACT_SLOPE),
                    lrelu(v.w * inv, ACT_SLOPE));
}

extern "C" void kernel_launch(void* const* d_in, const int* in_sizes, int n_in,
                              void* d_out, int out_size)
{
    const float* emb = (const float*)d_in[0];
    const int*   src1 = (const int*)d_in[1];
    const int*   dst1 = (const int*)d_in[2];
    const int*   src2 = (const int*)d_in[3];
    const int*   dst2 = (const int*)d_in[4];
    const float* Ws1 = (const float*)d_in[5];
    const float* bs1 = (const float*)d_in[6];
    const float* Wd1 = (const float*)d_in[7];
    const float* bd1 = (const float*)d_in[8];
    const float* at1 = (const float*)d_in[9];
    const float* Ws2 = (const float*)d_in[10];
    const float* bs2 = (const float*)d_in[11];
    const float* Wd2 = (const float*)d_in[12];
    const float* bd2 = (const float*)d_in[13];
    const float* at2 = (const float*)d_in[14];
    float* out = (float*)d_out;

    int n  = in_sizes[0] / D;
    int e1 = in_sizes[1];
    int e2 = in_sizes[3];

    dim3 tb(256);
    dim3 nb((unsigned)(((size_t)n * 4 + 255) / 256));
    // 16 edges per warp (2 rounds of 8)
    long long w1 = ((long long)e1 + 15) / 16;
    long long w2 = ((long long)e2 + 15) / 16;
    dim3 eb1((unsigned)((w1 * 32 + 255) / 256));
    dim3 eb2((unsigned)((w2 * 32 + 255) / 256));

    // layer 1
    k_feat1<<<nb, tb>>>(emb, Ws1, bs1, Wd1, bd1, n);
    k_edge <<<eb1, tb>>>(src1, dst1, at1, e1);
    // layer-1 epilogue + layer-2 feats
    k_mid  <<<nb, tb>>>(Ws2, bs2, Wd2, bd2, n);
    // layer 2
    k_edge <<<eb2, tb>>>(src2, dst2, at2, e2);
    k_fin  <<<nb, tb>>>(out, n);
}

// round 13
// speedup vs baseline: 1.0413x; 1.0397x over previous
#include <cuda_runtime.h>
#include <cuda_fp16.h>

#define NN 100000
#define EE 3200000
#define D 16
#define RS 32                 // accumulator row stride (floats) = 128B = one line
#define ATTN_SLOPE 0.2f
#define ACT_SLOPE 0.01f

// ---- scratch (device globals; no allocation allowed) ----
__device__ float  g_fs[NN * D];       // feat_src rows (fp32: feeds numer directly)
__device__ __half g_fdh[NN * D];      // feat_dst rows (fp16: only feeds the score)
__device__ float  g_acc[NN * RS];     // [numer[16], denom, pad...] one 128B line per node

static __device__ __forceinline__ float lrelu(float x, float s) {
    return x >= 0.0f ? x : s * x;
}

static __device__ __forceinline__ uint2 pack_half4(float4 v) {
    __half2 h01 = __floats2half2_rn(v.x, v.y);
    __half2 h23 = __floats2half2_rn(v.z, v.w);
    uint2 u;
    u.x = *reinterpret_cast<unsigned int*>(&h01);
    u.y = *reinterpret_cast<unsigned int*>(&h23);
    return u;
}
static __device__ __forceinline__ float4 unpack_half4(uint2 u) {
    float2 a = __half22float2(*reinterpret_cast<__half2*>(&u.x));
    float2 b = __half22float2(*reinterpret_cast<__half2*>(&u.y));
    return make_float4(a.x, a.y, b.x, b.y);
}

// ============================================================
// node kernels: 4 threads per node, each owns one float4 quarter
// ============================================================

__global__ void k_feat1(const float* __restrict__ h,
                        const float* __restrict__ Wsrc, const float* __restrict__ bsrc,
                        const float* __restrict__ Wdst, const float* __restrict__ bdst,
                        int n)
{
    __shared__ float4 sWs[D * 4], sWd[D * 4];   // [k][q]
    __shared__ float4 sbs[4], sbd[4];
    if (threadIdx.x < D * 4) {
        sWs[threadIdx.x] = reinterpret_cast<const float4*>(Wsrc)[threadIdx.x];
        sWd[threadIdx.x] = reinterpret_cast<const float4*>(Wdst)[threadIdx.x];
    }
    if (threadIdx.x < 4) {
        sbs[threadIdx.x] = reinterpret_cast<const float4*>(bsrc)[threadIdx.x];
        sbd[threadIdx.x] = reinterpret_cast<const float4*>(bdst)[threadIdx.x];
    }
    __syncthreads();
    int t  = blockIdx.x * blockDim.x + threadIdx.x;
    int nd = t >> 2;
    int q  = t & 3;
    if (nd >= n) return;

    const float4* hr = reinterpret_cast<const float4*>(h + (size_t)nd * D);
    float hv[D];
#pragma unroll
    for (int i = 0; i < 4; i++) {
        float4 v = hr[i];
        hv[4*i+0] = v.x; hv[4*i+1] = v.y; hv[4*i+2] = v.z; hv[4*i+3] = v.w;
    }
    float4 fs = sbs[q], fd = sbd[q];
#pragma unroll
    for (int k = 0; k < D; k++) {
        float hk = hv[k];
        float4 ws = sWs[k*4 + q];
        float4 wd = sWd[k*4 + q];
        fs.x = fmaf(hk, ws.x, fs.x); fs.y = fmaf(hk, ws.y, fs.y);
        fs.z = fmaf(hk, ws.z, fs.z); fs.w = fmaf(hk, ws.w, fs.w);
        fd.x = fmaf(hk, wd.x, fd.x); fd.y = fmaf(hk, wd.y, fd.y);
        fd.z = fmaf(hk, wd.z, fd.z); fd.w = fmaf(hk, wd.w, fd.w);
    }
    reinterpret_cast<float4*>(g_fs + (size_t)nd * D)[q] = fs;
    reinterpret_cast<uint2*>(g_fdh + (size_t)nd * D)[q] = pack_half4(fd);
    float4 z = make_float4(0.f, 0.f, 0.f, 0.f);
    float4* pa = reinterpret_cast<float4*>(g_acc + (size_t)nd * RS);
    pa[q] = z; pa[q + 4] = z;
}

__global__ void k_mid(const float* __restrict__ Wsrc, const float* __restrict__ bsrc,
                      const float* __restrict__ Wdst, const float* __restrict__ bdst,
                      int n)
{
    __shared__ float4 sWs[D * 4], sWd[D * 4];
    __shared__ float4 sbs[4], sbd[4];
    if (threadIdx.x < D * 4) {
        sWs[threadIdx.x] = reinterpret_cast<const float4*>(Wsrc)[threadIdx.x];
        sWd[threadIdx.x] = reinterpret_cast<const float4*>(Wdst)[threadIdx.x];
    }
    if (threadIdx.x < 4) {
        sbs[threadIdx.x] = reinterpret_cast<const float4*>(bsrc)[threadIdx.x];
        sbd[threadIdx.x] = reinterpret_cast<const float4*>(bdst)[threadIdx.x];
    }
    __syncthreads();
    int t  = blockIdx.x * blockDim.x + threadIdx.x;
    int nd = t >> 2;
    int q  = t & 3;
    if (nd >= n) return;

    const float* row = g_acc + (size_t)nd * RS;
    float dn  = row[16];
    float inv = dn > 0.0f ? 1.0f / dn : 0.0f;
    const float4* np = reinterpret_cast<const float4*>(row);
    float hv[D];
#pragma unroll
    for (int i = 0; i < 4; i++) {
        float4 v = np[i];
        hv[4*i+0] = lrelu(v.x * inv, ACT_SLOPE);
        hv[4*i+1] = lrelu(v.y * inv, ACT_SLOPE);
        hv[4*i+2] = lrelu(v.z * inv, ACT_SLOPE);
        hv[4*i+3] = lrelu(v.w * inv, ACT_SLOPE);
    }
    float4 fs = sbs[q], fd = sbd[q];
#pragma unroll
    for (int k = 0; k < D; k++) {
        float hk = hv[k];
        float4 ws = sWs[k*4 + q];
        float4 wd = sWd[k*4 + q];
        fs.x = fmaf(hk, ws.x, fs.x); fs.y = fmaf(hk, ws.y, fs.y);
        fs.z = fmaf(hk, ws.z, fs.z); fs.w = fmaf(hk, ws.w, fs.w);
        fd.x = fmaf(hk, wd.x, fd.x); fd.y = fmaf(hk, wd.y, fd.y);
        fd.z = fmaf(hk, wd.z, fd.z); fd.w = fmaf(hk, wd.w, fd.w);
    }
    reinterpret_cast<float4*>(g_fs + (size_t)nd * D)[q] = fs;
    reinterpret_cast<uint2*>(g_fdh + (size_t)nd * D)[q] = pack_half4(fd);
    float4 z = make_float4(0.f, 0.f, 0.f, 0.f);
    float4* pa = reinterpret_cast<float4*>(g_acc + (size_t)nd * RS);
    pa[q] = z; pa[q + 4] = z;
}

// ============================================================
// fused edge pass: 4 lanes per edge, 4 edges per thread.
// int4 index loads, 8 gathers in flight before any math,
// denoms for the 4 edges issued as ONE 4-lane red (lane q -> edge q).
// Softmax without max-shift (shift cancels exactly in numer/denom).
// ============================================================
__global__ void k_edge(const int* __restrict__ src, const int* __restrict__ dst,
                       const float* __restrict__ attn, int e)
{
    int t     = blockIdx.x * blockDim.x + threadIdx.x;
    int group = t >> 2;                 // handles 4 consecutive edges
    int q     = t & 3;
    long long e0 = (long long)group * 4;
    if (e0 >= e) return;

    float4 a = __ldg(reinterpret_cast<const float4*>(attn) + q);

    bool v1 = (e0 + 1) < e, v2 = (e0 + 2) < e, v3 = (e0 + 3) < e;

    int4 sv, dv;
    if (v3) {
        sv = __ldg(reinterpret_cast<const int4*>(src + e0));
        dv = __ldg(reinterpret_cast<const int4*>(dst + e0));
    } else {
        sv.x = __ldg(src + e0);
        sv.y = v1 ? __ldg(src + e0 + 1) : sv.x;
        sv.z = v2 ? __ldg(src + e0 + 2) : sv.x;
        sv.w = sv.x;
        dv.x = __ldg(dst + e0);
        dv.y = v1 ? __ldg(dst + e0 + 1) : dv.x;
        dv.z = v2 ? __ldg(dst + e0 + 2) : dv.x;
        dv.w = dv.x;
    }

    // all 8 gathers in flight before any dependent math
    float4 el0 = *(reinterpret_cast<const float4*>(g_fs + (size_t)sv.x * D) + q);
    float4 el1 = *(reinterpret_cast<const float4*>(g_fs + (size_t)sv.y * D) + q);
    float4 el2 = *(reinterpret_cast<const float4*>(g_fs + (size_t)sv.z * D) + q);
    float4 el3 = *(reinterpret_cast<const float4*>(g_fs + (size_t)sv.w * D) + q);
    uint2  eu0 = *(reinterpret_cast<const uint2*>(g_fdh + (size_t)dv.x * D) + q);
    uint2  eu1 = *(reinterpret_cast<const uint2*>(g_fdh + (size_t)dv.y * D) + q);
    uint2  eu2 = *(reinterpret_cast<const uint2*>(g_fdh + (size_t)dv.z * D) + q);
    uint2  eu3 = *(reinterpret_cast<const uint2*>(g_fdh + (size_t)dv.w * D) + q);
    float4 ed0 = unpack_half4(eu0);
    float4 ed1 = unpack_half4(eu1);
    float4 ed2 = unpack_half4(eu2);
    float4 ed3 = unpack_half4(eu3);

    float p0 = lrelu(el0.x + ed0.x, ATTN_SLOPE) * a.x
             + lrelu(el0.y + ed0.y, ATTN_SLOPE) * a.y
             + lrelu(el0.z + ed0.z, ATTN_SLOPE) * a.z
             + lrelu(el0.w + ed0.w, ATTN_SLOPE) * a.w;
    float p1 = lrelu(el1.x + ed1.x, ATTN_SLOPE) * a.x
             + lrelu(el1.y + ed1.y, ATTN_SLOPE) * a.y
             + lrelu(el1.z + ed1.z, ATTN_SLOPE) * a.z
             + lrelu(el1.w + ed1.w, ATTN_SLOPE) * a.w;
    float p2 = lrelu(el2.x + ed2.x, ATTN_SLOPE) * a.x
             + lrelu(el2.y + ed2.y, ATTN_SLOPE) * a.y
             + lrelu(el2.z + ed2.z, ATTN_SLOPE) * a.z
             + lrelu(el2.w + ed2.w, ATTN_SLOPE) * a.w;
    float p3 = lrelu(el3.x + ed3.x, ATTN_SLOPE) * a.x
             + lrelu(el3.y + ed3.y, ATTN_SLOPE) * a.y
             + lrelu(el3.z + ed3.z, ATTN_SLOPE) * a.z
             + lrelu(el3.w + ed3.w, ATTN_SLOPE) * a.w;

    const unsigned m = 0xFFFFFFFFu;
    p0 += __shfl_xor_sync(m, p0, 1);  p0 += __shfl_xor_sync(m, p0, 2);
    p1 += __shfl_xor_sync(m, p1, 1);  p1 += __shfl_xor_sync(m, p1, 2);
    p2 += __shfl_xor_sync(m, p2, 1);  p2 += __shfl_xor_sync(m, p2, 2);
    p3 += __shfl_xor_sync(m, p3, 1);  p3 += __shfl_xor_sync(m, p3, 2);

    float ex0 = __expf(p0);
    float ex1 = v1 ? __expf(p1) : 0.0f;   // invalid edges contribute 0
    float ex2 = v2 ? __expf(p2) : 0.0f;
    float ex3 = v3 ? __expf(p3) : 0.0f;

    // numer: lane q reds quarter q of each edge's accumulator line
    float* pn0 = g_acc + (size_t)dv.x * RS + q * 4;
    asm volatile("red.global.add.v4.f32 [%0], {%1, %2, %3, %4};"
                 :: "l"(pn0), "f"(ex0 * el0.x), "f"(ex0 * el0.y),
                    "f"(ex0 * el0.z), "f"(ex0 * el0.w) : "memory");
    if (v1) {
        float* pn1 = g_acc + (size_t)dv.y * RS + q * 4;
        asm volatile("red.global.add.v4.f32 [%0], {%1, %2, %3, %4};"
                     :: "l"(pn1), "f"(ex1 * el1.x), "f"(ex1 * el1.y),
                        "f"(ex1 * el1.z), "f"(ex1 * el1.w) : "memory");
    }
    if (v2) {
        float* pn2 = g_acc + (size_t)dv.z * RS + q * 4;
        asm volatile("red.global.add.v4.f32 [%0], {%1, %2, %3, %4};"
                     :: "l"(pn2), "f"(ex2 * el2.x), "f"(ex2 * el2.y),
                        "f"(ex2 * el2.z), "f"(ex2 * el2.w) : "memory");
    }
    if (v3) {
        float* pn3 = g_acc + (size_t)dv.w * RS + q * 4;
        asm volatile("red.global.add.v4.f32 [%0], {%1, %2, %3, %4};"
                     :: "l"(pn3), "f"(ex3 * el3.x), "f"(ex3 * el3.y),
                        "f"(ex3 * el3.z), "f"(ex3 * el3.w) : "memory");
    }

    // denom: ONE red instruction, lane q carries edge q's denom
    {
        int   dq = (q == 0) ? dv.x : (q == 1) ? dv.y : (q == 2) ? dv.z : dv.w;
        float xq = (q == 0) ? ex0  : (q == 1) ? ex1  : (q == 2) ? ex2  : ex3;
        atomicAdd(g_acc + (size_t)dq * RS + 16, xq);   // ex==0 for invalid edges
    }
}

// ---- layer-2 epilogue -> output ----
__global__ void k_fin(float* __restrict__ out, int n)
{
    int t  = blockIdx.x * blockDim.x + threadIdx.x;
    int nd = t >> 2;
    int q  = t & 3;
    if (nd >= n) return;
    const float* row = g_acc + (size_t)nd * RS;
    float dn  = row[16];
    float inv = dn > 0.0f ? 1.0f / dn : 0.0f;
    float4 v = reinterpret_cast<const float4*>(row)[q];
    reinterpret_cast<float4*>(out + (size_t)nd * D)[q] =
        make_float4(lrelu(v.x * inv, ACT_SLOPE),
                    lrelu(v.y * inv, ACT_SLOPE),
                    lrelu(v.z * inv, ACT_SLOPE),
                    lrelu(v.w * inv, ACT_SLOPE));
}

extern "C" void kernel_launch(void* const* d_in, const int* in_sizes, int n_in,
                              void* d_out, int out_size)
{
    const float* emb = (const float*)d_in[0];
    const int*   src1 = (const int*)d_in[1];
    const int*   dst1 = (const int*)d_in[2];
    const int*   src2 = (const int*)d_in[3];
    const int*   dst2 = (const int*)d_in[4];
    const float* Ws1 = (const float*)d_in[5];
    const float* bs1 = (const float*)d_in[6];
    const float* Wd1 = (const float*)d_in[7];
    const float* bd1 = (const float*)d_in[8];
    const float* at1 = (const float*)d_in[9];
    const float* Ws2 = (const float*)d_in[10];
    const float* bs2 = (const float*)d_in[11];
    const float* Wd2 = (const float*)d_in[12];
    const float* bd2 = (const float*)d_in[13];
    const float* at2 = (const float*)d_in[14];
    float* out = (float*)d_out;

    int n  = in_sizes[0] / D;
    int e1 = in_sizes[1];
    int e2 = in_sizes[3];

    dim3 tb(256);
    dim3 nb((unsigned)(((size_t)n * 4 + 255) / 256));
    // 4 lanes per edge, 4 edges per thread
    long long g1 = (((long long)e1 + 3) / 4) * 4;
    long long g2 = (((long long)e2 + 3) / 4) * 4;
    dim3 eb1((unsigned)((g1 + 255) / 256));
    dim3 eb2((unsigned)((g2 + 255) / 256));

    // layer 1
    k_feat1<<<nb, tb>>>(emb, Ws1, bs1, Wd1, bd1, n);
    k_edge <<<eb1, tb>>>(src1, dst1, at1, e1);
    // layer-1 epilogue + layer-2 feats
    k_mid  <<<nb, tb>>>(Ws2, bs2, Wd2, bd2, n);
    // layer 2
    k_edge <<<eb2, tb>>>(src2, dst2, at2, e2);
    k_fin  <<<nb, tb>>>(out, n);
}